// round 16
// baseline (speedup 1.0000x reference)
#include <cuda_runtime.h>
#include <cuda_fp16.h>
#include <cstdint>
#include <cstddef>

// ---------------------------------------------------------------------------
// Problem dims
// ---------------------------------------------------------------------------
#define Bc 256
#define Tc 256
#define Dc 128
#define Ec 256
#define Hc 256
#define Ac 18

static constexpr size_t N_LOGITS = (size_t)Bc * Tc * Ac;
static constexpr size_t NGATE    = (size_t)Bc * Tc * Hc;
static constexpr size_t OFF_LOGITS = 0;
static constexpr size_t OFF_VALUES = OFF_LOGITS + N_LOGITS;
static constexpr size_t OFF_HT     = OFF_VALUES + (size_t)Bc * Tc;
static constexpr size_t OFF_CT     = OFF_HT + (size_t)Bc * Hc;
static constexpr size_t OFF_AR     = OFF_CT + (size_t)Bc * Hc;
static constexpr size_t OFF_TAR    = OFF_AR + 1;
static constexpr size_t OFF_I      = OFF_TAR + 1;
static constexpr size_t OFF_Fg     = OFF_I + NGATE;
static constexpr size_t OFF_Gg     = OFF_Fg + NGATE;
static constexpr size_t OFF_Og     = OFF_Gg + NGATE;
static constexpr size_t OFF_CS     = OFF_Og + NGATE;
static constexpr size_t OFF_HS     = OFF_CS + NGATE;

// ---------------------------------------------------------------------------
// Device scratch
// ---------------------------------------------------------------------------
__device__ float  g_pre [(size_t)Bc * Tc * 4 * Hc];
__device__ float  g_bias[4 * Hc];
__device__ float  g_part[256];
__device__ __half g_obs_h[(size_t)Bc * Tc * Dc];
__device__ __half g_obs_l[(size_t)Bc * Tc * Dc];
__device__ __half g_e1h[(size_t)Bc * Tc * Ec];
__device__ __half g_e1l[(size_t)Bc * Tc * Ec];
__device__ __half g_e2h[(size_t)Bc * Tc * Ec];
__device__ __half g_e2l[(size_t)Bc * Tc * Ec];
__device__ __half g_w1h[Ec * Dc];
__device__ __half g_w2h[Ec * Ec];
__device__ __half g_wih_h[4 * Hc * Ec];

extern __shared__ __align__(1024) char dynsmem[];

// ---------------------------------------------------------------------------
// Math helpers
// ---------------------------------------------------------------------------
__device__ __forceinline__ float sigm(float x) {
    return __fdividef(1.0f, 1.0f + __expf(-x));
}
__device__ __forceinline__ float tanh_f(float x) {
    return 1.0f - __fdividef(2.0f, __expf(2.0f * x) + 1.0f);
}
__device__ __forceinline__ float silu(float x) { return x * sigm(x); }

__device__ __forceinline__ uint32_t smem_u32(const void* p) {
    uint32_t a;
    asm("{ .reg .u64 t; cvta.to.shared.u64 t, %1; cvt.u32.u64 %0, t; }" : "=r"(a) : "l"(p));
    return a;
}

// ---------------------------------------------------------------------------
// warp-MMA + cp.async primitives (baseline PTX, valid at target sm_100)
// ---------------------------------------------------------------------------
__device__ __forceinline__ void ldsm4(uint32_t* r, uint32_t addr) {
    asm volatile("ldmatrix.sync.aligned.m8n8.x4.shared.b16 {%0,%1,%2,%3}, [%4];"
                 : "=r"(r[0]), "=r"(r[1]), "=r"(r[2]), "=r"(r[3]) : "r"(addr));
}
__device__ __forceinline__ void ldsm2(uint32_t* r, uint32_t addr) {
    asm volatile("ldmatrix.sync.aligned.m8n8.x2.shared.b16 {%0,%1}, [%2];"
                 : "=r"(r[0]), "=r"(r[1]) : "r"(addr));
}
__device__ __forceinline__ void mma16816h(float* d, const uint32_t* a, const uint32_t* b) {
    asm volatile("mma.sync.aligned.m16n8k16.row.col.f32.f16.f16.f32 "
                 "{%0,%1,%2,%3}, {%4,%5,%6,%7}, {%8,%9}, {%0,%1,%2,%3};"
                 : "+f"(d[0]), "+f"(d[1]), "+f"(d[2]), "+f"(d[3])
                 : "r"(a[0]), "r"(a[1]), "r"(a[2]), "r"(a[3]), "r"(b[0]), "r"(b[1]));
}
__device__ __forceinline__ void cp16(uint32_t dst, const void* src) {
    asm volatile("cp.async.cg.shared.global [%0], [%1], 16;" :: "r"(dst), "l"(src));
}
#define CP_COMMIT() asm volatile("cp.async.commit_group;" ::: "memory")

// ---------------------------------------------------------------------------
// fp32 -> fp16 conversions
// ---------------------------------------------------------------------------
__global__ void conv_split_h(const float* __restrict__ in, __half* __restrict__ h,
                             __half* __restrict__ l, int n)
{
    int i = blockIdx.x * blockDim.x + threadIdx.x;
    if (i >= n) return;
    float x = in[i];
    __half hb = __float2half_rn(x);
    h[i] = hb;
    l[i] = __float2half_rn(x - __half2float(hb));
}
__global__ void conv_h(const float* __restrict__ in, __half* __restrict__ h, int n)
{
    int i = blockIdx.x * blockDim.x + threadIdx.x;
    if (i >= n) return;
    h[i] = __float2half_rn(in[i]);
}

// ---------------------------------------------------------------------------
// split-fp16 tensor-core GEMM (unchanged from R8/R10/R14 passing kernel)
// ---------------------------------------------------------------------------
#define PA_H 0
#define PA_L 10240
#define PB_H 20480
#define GSTAGE 30720
#define GDATA_OFF 512
#define GEMM_SMEM_TOT (GDATA_OFF + 2 * GSTAGE)

__device__ __forceinline__ void gemm_load_stage(
    uint32_t sbase,
    const __half* __restrict__ Ah, const __half* __restrict__ Al,
    const __half* __restrict__ Wh,
    int m0, int n0, int K, int k0, int tid)
{
    #pragma unroll
    for (int i = 0; i < 2; ++i) {
        int idx = tid + (i << 8);
        int row = idx >> 2, c = idx & 3;
        uint32_t d = (uint32_t)(row * 80 + c * 16);
        size_t ga = (size_t)(m0 + row) * K + k0 + c * 8;
        size_t gb = (size_t)(n0 + row) * K + k0 + c * 8;
        cp16(sbase + PA_H + d, Ah + ga);
        cp16(sbase + PA_L + d, Al + ga);
        cp16(sbase + PB_H + d, Wh + gb);
    }
}

__global__ __launch_bounds__(256)
void gemm_mma(const __half* __restrict__ Ah, const __half* __restrict__ Al,
              const __half* __restrict__ Wh,
              const float* __restrict__ bias, float* __restrict__ outF,
              __half* __restrict__ outH, __half* __restrict__ outL,
              int K, int N, int mode)
{
    const uint32_t sb = smem_u32(dynsmem);
    float* sbias = (float*)dynsmem;

    const int tid  = threadIdx.x;
    const int lane = tid & 31;
    const int w    = tid >> 5;
    const int wm   = w >> 2;
    const int wn   = w & 3;
    const int m0   = blockIdx.x * 128;
    const int n0   = blockIdx.y * 128;

    if (tid < 128) sbias[tid] = bias[n0 + tid];

    const int aro  = (lane & 7) + ((lane >> 3) & 1) * 8;
    const int ac16 = (lane >> 4) & 1;
    const int bl8  = lane & 15;
    const int bro  = bl8 & 7;
    const int bc16 = (bl8 >> 3) & 1;

    const uint32_t aBase = (uint32_t)aro * 80 + ac16 * 16;
    const uint32_t bBase = (uint32_t)bro * 80 + bc16 * 16;

    float acc[4][4][4];
    #pragma unroll
    for (int mt = 0; mt < 4; ++mt)
        #pragma unroll
        for (int nt = 0; nt < 4; ++nt)
            #pragma unroll
            for (int r = 0; r < 4; ++r) acc[mt][nt][r] = 0.0f;

    const int NCH = K >> 5;
    gemm_load_stage(sb + GDATA_OFF, Ah, Al, Wh, m0, n0, K, 0, tid);
    CP_COMMIT();

    for (int ch = 0; ch < NCH; ++ch) {
        if (ch + 1 < NCH) {
            gemm_load_stage(sb + GDATA_OFF + ((ch + 1) & 1) * GSTAGE,
                            Ah, Al, Wh, m0, n0, K, (ch + 1) << 5, tid);
            CP_COMMIT();
            asm volatile("cp.async.wait_group 1;" ::: "memory");
        } else {
            asm volatile("cp.async.wait_group 0;" ::: "memory");
        }
        __syncthreads();

        const uint32_t st = sb + GDATA_OFF + (ch & 1) * GSTAGE;
        #pragma unroll
        for (int ks = 0; ks < 2; ++ks) {
            uint32_t bh[4][2];
            #pragma unroll
            for (int nt = 0; nt < 4; ++nt) {
                uint32_t o = bBase + (uint32_t)(wn * 32 + nt * 8) * 80 + ks * 32;
                ldsm2(bh[nt], st + PB_H + o);
            }
            #pragma unroll
            for (int mt = 0; mt < 4; ++mt) {
                uint32_t ah[4], al[4];
                uint32_t o = aBase + (uint32_t)(wm * 64 + mt * 16) * 80 + ks * 32;
                ldsm4(ah, st + PA_H + o);
                ldsm4(al, st + PA_L + o);
                #pragma unroll
                for (int nt = 0; nt < 4; ++nt) {
                    mma16816h(acc[mt][nt], ah, bh[nt]);
                    mma16816h(acc[mt][nt], al, bh[nt]);
                }
            }
        }
        __syncthreads();
    }

    #pragma unroll
    for (int mt = 0; mt < 4; ++mt) {
        const int r0 = m0 + wm * 64 + mt * 16 + (lane >> 2);
        #pragma unroll
        for (int nt = 0; nt < 4; ++nt) {
            const int cl = wn * 32 + nt * 8 + (lane & 3) * 2;
            const int c  = n0 + cl;
            float v0 = acc[mt][nt][0] + sbias[cl];
            float v1 = acc[mt][nt][1] + sbias[cl + 1];
            float v2 = acc[mt][nt][2] + sbias[cl];
            float v3 = acc[mt][nt][3] + sbias[cl + 1];
            if (mode == 0) {
                *(float2*)&outF[(size_t)r0 * N + c]       = make_float2(v0, v1);
                *(float2*)&outF[(size_t)(r0 + 8) * N + c] = make_float2(v2, v3);
            } else {
                v0 = silu(v0); v1 = silu(v1); v2 = silu(v2); v3 = silu(v3);
                __half h0 = __float2half_rn(v0), h1 = __float2half_rn(v1);
                __half h2 = __float2half_rn(v2), h3 = __float2half_rn(v3);
                __half l0 = __float2half_rn(v0 - __half2float(h0));
                __half l1 = __float2half_rn(v1 - __half2float(h1));
                __half l2 = __float2half_rn(v2 - __half2float(h2));
                __half l3 = __float2half_rn(v3 - __half2float(h3));
                size_t o0 = (size_t)r0 * N + c, o1 = (size_t)(r0 + 8) * N + c;
                *(__half2*)&outH[o0] = __halves2half2(h0, h1);
                *(__half2*)&outL[o0] = __halves2half2(l0, l1);
                *(__half2*)&outH[o1] = __halves2half2(h2, h3);
                *(__half2*)&outL[o1] = __halves2half2(l2, l3);
            }
        }
    }
}

// ---------------------------------------------------------------------------
// bias prep
// ---------------------------------------------------------------------------
__global__ void prep_bias(const float* __restrict__ bih, const float* __restrict__ bhh)
{
    int i = threadIdx.x;
    g_bias[i] = bih[i] + bhh[i];
}

// ---------------------------------------------------------------------------
// Tensor-core persistent cluster LSTM (R14 passing kernel) + coalesced
// gate stores via smem staging. Gate regions are offset by 2 floats from
// 16B alignment, so writeback uses float2 (8B-aligned) stores; HT/CT use
// float4 (their regions are 16B aligned).
// ---------------------------------------------------------------------------
#define HSTR  264
#define SM_BH 0                            // Whh hi [128][HSTR]       (67584 B)
#define SM_A0 (128 * HSTR * 2)             // h buf0: hi[16]+lo[16]    (67584)
#define ABUF  (2 * 16 * HSTR * 2)          // 16896 per buffer
#define SM_A1 (SM_A0 + ABUF)               // 84480
#define SM_STG (SM_A1 + ABUF)              // 101376
#define SM_GST (SM_STG + 2 * 16 * 32 * 2)  // 103424: gates [6][16][36] floats
#define LSTM_SMEM (SM_GST + 6 * 16 * 36 * 4)   // 117248

__global__ void __cluster_dims__(8, 1, 1) __launch_bounds__(128, 1)
lstm_kernel(const float* __restrict__ hxs, const float* __restrict__ cxs,
            const float* __restrict__ w_hh, float* __restrict__ out)
{
    char* smc = dynsmem;
    const uint32_t sb = smem_u32(dynsmem);
    const int tid  = threadIdx.x;
    const int lane = tid & 31;
    const int w    = tid >> 5;
    const int grp  = blockIdx.x >> 3;
    const int rank = blockIdx.x & 7;
    const int b0   = grp * 16;
    const int u0   = rank * 32;

    // Whh hi plane: row n = lu*4 + q  <-  w_hh[q*256 + u0 + lu][:]
    {
        int lu = tid >> 2, q = tid & 3;
        const float* src = &w_hh[(size_t)((q << 8) + u0 + lu) * Hc];
        __half* bh = (__half*)(smc + SM_BH) + tid * HSTR;
        for (int k = 0; k < Hc; k += 4) {
            float4 v = *(const float4*)&src[k];
            bh[k + 0] = __float2half_rn(v.x);
            bh[k + 1] = __float2half_rn(v.y);
            bh[k + 2] = __float2half_rn(v.z);
            bh[k + 3] = __float2half_rn(v.w);
        }
    }
    // init h buffer 0 from hxs (hi/lo planes)
    for (int idx = tid; idx < 16 * 64; idx += 128) {
        int row = idx >> 6, k4 = (idx & 63) << 2;
        float4 v = *(const float4*)&hxs[(size_t)(b0 + row) * Hc + k4];
        __half* ah = (__half*)(smc + SM_A0) + row * HSTR + k4;
        __half* al = (__half*)(smc + SM_A0 + ABUF / 2) + row * HSTR + k4;
        __half h0 = __float2half_rn(v.x), h1 = __float2half_rn(v.y);
        __half h2 = __float2half_rn(v.z), h3 = __float2half_rn(v.w);
        ah[0] = h0; ah[1] = h1; ah[2] = h2; ah[3] = h3;
        al[0] = __float2half_rn(v.x - __half2float(h0));
        al[1] = __float2half_rn(v.y - __half2float(h1));
        al[2] = __float2half_rn(v.z - __half2float(h2));
        al[3] = __float2half_rn(v.w - __half2float(h3));
    }

    unsigned ra0[8], ra1[8];
    {
        unsigned a0 = sb + SM_A0, a1 = sb + SM_A1;
        #pragma unroll
        for (int rk = 0; rk < 8; ++rk) {
            asm volatile("mapa.shared::cluster.u32 %0, %1, %2;" : "=r"(ra0[rk]) : "r"(a0), "r"(rk));
            asm volatile("mapa.shared::cluster.u32 %0, %1, %2;" : "=r"(ra1[rk]) : "r"(a1), "r"(rk));
        }
    }

    // thread/cell geometry (R9/R10-proven)
    const int d_    = (lane & 3) >> 1;
    const bool isT0 = ((lane & 1) == 0);
    const int r1    = lane >> 2;
    const int myrow = r1 + ((lane & 1) << 3);
    const int q0    = (lane & 1) ? 2 : 0;

    float c[4], hp[4];
    int lcs[4];
    #pragma unroll
    for (int s = 0; s < 4; ++s) {
        lcs[s] = 8 * w + 2 * s + d_;
        c[s]  = cxs[(size_t)(b0 + myrow) * Hc + u0 + lcs[s]];
        hp[s] = 0.0f;
    }
    float ar = 0.0f, tar = 0.0f;

    const uint32_t aoff = (uint32_t)((lane & 7) + ((lane >> 3) & 1) * 8) * 528
                        + (uint32_t)((lane >> 4) & 1) * 16;
    const uint32_t bofs0 = (uint32_t)(32 * w) * 528 + aoff;
    const uint32_t bofs1 = (uint32_t)(32 * w + 16) * 528 + aoff;

    __half* stage_h = (__half*)(smc + SM_STG);
    __half* stage_l = (__half*)(smc + SM_STG + 1024);
    float*  gstg    = (float*)(smc + SM_GST);     // [6][16][36]

    __syncthreads();

    // prefetch g_pre for t=0
    float pre[4][4];
    {
        size_t p1 = ((size_t)((b0 + r1) * Tc)) * 1024;
        size_t p2 = ((size_t)((b0 + r1 + 8) * Tc)) * 1024;
        #pragma unroll
        for (int s = 0; s < 4; ++s) {
            int col = q0 * 256 + u0 + lcs[s];
            pre[s][0] = g_pre[p1 + col]; pre[s][1] = g_pre[p1 + col + 256];
            pre[s][2] = g_pre[p2 + col]; pre[s][3] = g_pre[p2 + col + 256];
        }
    }

    int cur = 0;
    for (int t = 0; t < Tc; ++t) {
        float acc[4][4], acc2[4][4];
        #pragma unroll
        for (int s = 0; s < 4; ++s) {
            acc[s][0] = pre[s][0]; acc[s][1] = pre[s][1];
            acc[s][2] = pre[s][2]; acc[s][3] = pre[s][3];
            acc2[s][0] = 0.0f; acc2[s][1] = 0.0f;
            acc2[s][2] = 0.0f; acc2[s][3] = 0.0f;
        }

        const uint32_t abh = sb + (cur ? SM_A1 : SM_A0);
        const uint32_t abl = abh + ABUF / 2;

        // software-pipelined mainloop (R14-proven)
        uint32_t fah[2][4], fal[2][4], f0[2][4], f1[2][4];
        ldsm4(fah[0], abh + aoff);
        ldsm4(fal[0], abl + aoff);
        ldsm4(f0[0],  sb + SM_BH + bofs0);
        ldsm4(f1[0],  sb + SM_BH + bofs1);

        #pragma unroll
        for (int kc = 0; kc < 16; ++kc) {
            const int cb = kc & 1, nb = cb ^ 1;
            if (kc < 15) {
                const uint32_t ko = (uint32_t)(kc + 1) * 32;
                ldsm4(fah[nb], abh + aoff + ko);
                ldsm4(fal[nb], abl + aoff + ko);
                ldsm4(f0[nb],  sb + SM_BH + bofs0 + ko);
                ldsm4(f1[nb],  sb + SM_BH + bofs1 + ko);
            }
            uint32_t bh[4][2] = {{f0[cb][0], f0[cb][2]}, {f0[cb][1], f0[cb][3]},
                                 {f1[cb][0], f1[cb][2]}, {f1[cb][1], f1[cb][3]}};
            float (*A)[4] = cb ? acc2 : acc;
            #pragma unroll
            for (int s = 0; s < 4; ++s) {
                mma16816h(A[s], fah[cb], bh[s]);
                mma16816h(A[s], fal[cb], bh[s]);
            }
        }
        #pragma unroll
        for (int s = 0; s < 4; ++s) {
            acc[s][0] += acc2[s][0]; acc[s][1] += acc2[s][1];
            acc[s][2] += acc2[s][2]; acc[s][3] += acc2[s][3];
        }

        // pointwise cell -> smem staging (gates) + h staging
        #pragma unroll
        for (int s = 0; s < 4; ++s) {
            float sh1 = __shfl_xor_sync(0xffffffffu, isT0 ? acc[s][2] : acc[s][0], 1);
            float sh2 = __shfl_xor_sync(0xffffffffu, isT0 ? acc[s][3] : acc[s][1], 1);
            float i_, f_, g_, o_;
            if (isT0) { i_ = acc[s][0]; f_ = acc[s][1]; g_ = sh1; o_ = sh2; }
            else      { g_ = acc[s][2]; o_ = acc[s][3]; i_ = sh1; f_ = sh2; }

            float iv = sigm(i_), fv = sigm(f_), gv = tanh_f(g_), ov = sigm(o_);
            float c2 = fmaf(fv, c[s], iv * gv);
            float h2 = ov * tanh_f(c2);
            c[s] = c2;
            ar = fmaf(h2, h2, ar);
            float dd = h2 - hp[s];
            if (t > 0) tar = fmaf(dd, dd, tar);
            hp[s] = h2;

            const int sidx = myrow * 36 + lcs[s];
            gstg[0 * 576 + sidx] = iv;
            gstg[1 * 576 + sidx] = fv;
            gstg[2 * 576 + sidx] = gv;
            gstg[3 * 576 + sidx] = ov;
            gstg[4 * 576 + sidx] = c2;
            gstg[5 * 576 + sidx] = h2;

            __half hh = __float2half_rn(h2);
            stage_h[myrow * 32 + lcs[s]] = hh;
            stage_l[myrow * 32 + lcs[s]] = __float2half_rn(h2 - __half2float(hh));
        }

        __syncthreads();

        // push own 32-unit h chunk (hi+lo planes) to all 8 ranks' next buffer
        {
            const int p   = tid >> 6;
            const int rem = tid & 63;
            const int row = rem >> 2;
            const int ch  = rem & 3;
            uint4 v = *(const uint4*)(smc + SM_STG + p * 1024 + (row * 32 + ch * 8) * 2);
            const uint32_t dsto = (uint32_t)p * (ABUF / 2) + (uint32_t)row * 528
                                + (uint32_t)(u0 + ch * 8) * 2;
            const unsigned* rbuf = cur ? ra0 : ra1;
            #pragma unroll
            for (int rk = 0; rk < 8; ++rk) {
                asm volatile("st.shared::cluster.v4.b32 [%0], {%1,%2,%3,%4};"
                             :: "r"(rbuf[rk] + dsto), "r"(v.x), "r"(v.y), "r"(v.z), "r"(v.w)
                             : "memory");
            }
        }

        asm volatile("barrier.cluster.arrive.aligned;" ::: "memory");

        // hidden inside arrive->wait: coalesced gate writes (float2: gate
        // regions are 8B- but not 16B-aligned) + pre prefetch
        {
            const size_t goffs[6] = {OFF_I, OFF_Fg, OFF_Gg, OFF_Og, OFF_CS, OFF_HS};
            const int row = tid >> 3;              // 0..15
            const int j   = (tid & 7) * 4;         // 0..28
            const size_t rbase = ((size_t)((b0 + row) * Tc + t)) * Hc + u0 + j;
            #pragma unroll
            for (int g = 0; g < 6; ++g) {
                const float* sv = &gstg[g * 576 + row * 36 + j];
                float2 va = make_float2(sv[0], sv[1]);
                float2 vb = make_float2(sv[2], sv[3]);
                __stcs((float2*)&out[goffs[g] + rbase],     va);
                __stcs((float2*)&out[goffs[g] + rbase + 2], vb);
                if (t == Tc - 1 && g >= 4) {
                    const size_t hoff = (g == 4 ? OFF_CT : OFF_HT)
                                      + (size_t)(b0 + row) * Hc + u0 + j;
                    *(float4*)&out[hoff] = make_float4(va.x, va.y, vb.x, vb.y);
                }
            }
        }
        if (t + 1 < Tc) {
            size_t p1 = ((size_t)((b0 + r1) * Tc + t + 1)) * 1024;
            size_t p2 = ((size_t)((b0 + r1 + 8) * Tc + t + 1)) * 1024;
            #pragma unroll
            for (int s = 0; s < 4; ++s) {
                int col = q0 * 256 + u0 + lcs[s];
                pre[s][0] = g_pre[p1 + col]; pre[s][1] = g_pre[p1 + col + 256];
                pre[s][2] = g_pre[p2 + col]; pre[s][3] = g_pre[p2 + col + 256];
            }
        }

        asm volatile("barrier.cluster.wait.aligned;" ::: "memory");
        cur ^= 1;
    }

    __shared__ float red[128];
    red[tid] = ar; __syncthreads();
    for (int o = 64; o > 0; o >>= 1) { if (tid < o) red[tid] += red[tid + o]; __syncthreads(); }
    if (tid == 0) g_part[blockIdx.x] = red[0];
    __syncthreads();
    red[tid] = tar; __syncthreads();
    for (int o = 64; o > 0; o >>= 1) { if (tid < o) red[tid] += red[tid + o]; __syncthreads(); }
    if (tid == 0) g_part[128 + blockIdx.x] = red[0];
}

// ---------------------------------------------------------------------------
// loss finalize
// ---------------------------------------------------------------------------
__global__ void loss_fin(float* __restrict__ out)
{
    __shared__ float r[128];
    int tid = threadIdx.x;
    r[tid] = g_part[tid]; __syncthreads();
    for (int o = 64; o > 0; o >>= 1) { if (tid < o) r[tid] += r[tid + o]; __syncthreads(); }
    float sar = r[0]; __syncthreads();
    r[tid] = g_part[128 + tid]; __syncthreads();
    for (int o = 64; o > 0; o >>= 1) { if (tid < o) r[tid] += r[tid + o]; __syncthreads(); }
    if (tid == 0) {
        out[OFF_AR]  = sar * (0.01f / 16777216.0f);
        out[OFF_TAR] = r[0] * (0.01f / 16711680.0f);
    }
}

// ---------------------------------------------------------------------------
// actor/critic heads
// ---------------------------------------------------------------------------
__global__ __launch_bounds__(256)
void head_kernel(const float* __restrict__ aw, const float* __restrict__ ab,
                 const float* __restrict__ cw, const float* __restrict__ cb,
                 float* __restrict__ out)
{
    __shared__ float ws[19 * 256];
    const int tid = threadIdx.x;
    for (int i = tid; i < Ac * Hc; i += 256) ws[i] = aw[i];
    for (int i = tid; i < Hc; i += 256) ws[Ac * Hc + i] = cw[i];
    __syncthreads();

    const int warp = tid >> 5, lane = tid & 31;
    const size_t m = (size_t)blockIdx.x * 8 + warp;
    const float* h = &out[OFF_HS + m * Hc];

    float p[19];
    #pragma unroll
    for (int o = 0; o < 19; ++o) p[o] = 0.0f;
    #pragma unroll
    for (int kk = 0; kk < 8; ++kk) {
        int k = lane + kk * 32;
        float hv = h[k];
        #pragma unroll
        for (int o = 0; o < 19; ++o) p[o] = fmaf(hv, ws[o * 256 + k], p[o]);
    }
    #pragma unroll
    for (int o = 0; o < 19; ++o)
        #pragma unroll
        for (int off = 16; off > 0; off >>= 1)
            p[o] += __shfl_down_sync(0xffffffffu, p[o], off);

    if (lane == 0) {
        #pragma unroll
        for (int o = 0; o < Ac; ++o)
            out[OFF_LOGITS + m * Ac + o] = p[o] + ab[o];
        out[OFF_VALUES + m] = p[18] + cb[0];
    }
}

// ---------------------------------------------------------------------------
// launcher
// ---------------------------------------------------------------------------
extern "C" void kernel_launch(void* const* d_in, const int* in_sizes, int n_in,
                              void* d_out, int out_size)
{
    const float* obs    = (const float*)d_in[0];
    const float* hxs    = (const float*)d_in[1];
    const float* cxs    = (const float*)d_in[2];
    const float* enc_w1 = (const float*)d_in[3];
    const float* enc_b1 = (const float*)d_in[4];
    const float* enc_w2 = (const float*)d_in[5];
    const float* enc_b2 = (const float*)d_in[6];
    const float* w_ih   = (const float*)d_in[7];
    const float* w_hh   = (const float*)d_in[8];
    const float* b_ih   = (const float*)d_in[9];
    const float* b_hh   = (const float*)d_in[10];
    const float* aw     = (const float*)d_in[11];
    const float* ab     = (const float*)d_in[12];
    const float* cw     = (const float*)d_in[13];
    const float* cb     = (const float*)d_in[14];
    float* out = (float*)d_out;

    void *p_pre, *p_bias;
    void *p_oh, *p_ol, *p_e1h, *p_e1l, *p_e2h, *p_e2l;
    void *p_w1h, *p_w2h, *p_wihh;
    cudaGetSymbolAddress(&p_pre,  g_pre);
    cudaGetSymbolAddress(&p_bias, g_bias);
    cudaGetSymbolAddress(&p_oh,   g_obs_h);  cudaGetSymbolAddress(&p_ol,   g_obs_l);
    cudaGetSymbolAddress(&p_e1h,  g_e1h);    cudaGetSymbolAddress(&p_e1l,  g_e1l);
    cudaGetSymbolAddress(&p_e2h,  g_e2h);    cudaGetSymbolAddress(&p_e2l,  g_e2l);
    cudaGetSymbolAddress(&p_w1h,  g_w1h);
    cudaGetSymbolAddress(&p_w2h,  g_w2h);
    cudaGetSymbolAddress(&p_wihh, g_wih_h);

    cudaFuncSetAttribute(lstm_kernel,
                         cudaFuncAttributeMaxDynamicSharedMemorySize, LSTM_SMEM);
    cudaFuncSetAttribute(gemm_mma,
                         cudaFuncAttributeMaxDynamicSharedMemorySize, GEMM_SMEM_TOT);

    const int M = Bc * Tc;  // 65536

    {
        int n;
        n = M * Dc;      conv_split_h<<<(n + 255) / 256, 256>>>(obs, (__half*)p_oh, (__half*)p_ol, n);
        n = Ec * Dc;     conv_h<<<(n + 255) / 256, 256>>>(enc_w1, (__half*)p_w1h, n);
        n = Ec * Ec;     conv_h<<<(n + 255) / 256, 256>>>(enc_w2, (__half*)p_w2h, n);
        n = 4 * Hc * Ec; conv_h<<<(n + 255) / 256, 256>>>(w_ih,   (__half*)p_wihh, n);
    }
    prep_bias<<<1, 1024>>>(b_ih, b_hh);

    gemm_mma<<<dim3(M / 128, Ec / 128), 256, GEMM_SMEM_TOT>>>(
        (const __half*)p_oh, (const __half*)p_ol, (const __half*)p_w1h,
        enc_b1, nullptr, (__half*)p_e1h, (__half*)p_e1l, Dc, Ec, 1);
    gemm_mma<<<dim3(M / 128, Ec / 128), 256, GEMM_SMEM_TOT>>>(
        (const __half*)p_e1h, (const __half*)p_e1l, (const __half*)p_w2h,
        enc_b2, nullptr, (__half*)p_e2h, (__half*)p_e2l, Ec, Ec, 1);
    gemm_mma<<<dim3(M / 128, (4 * Hc) / 128), 256, GEMM_SMEM_TOT>>>(
        (const __half*)p_e2h, (const __half*)p_e2l, (const __half*)p_wihh,
        (const float*)p_bias, (float*)p_pre, nullptr, nullptr, Ec, 4 * Hc, 0);

    lstm_kernel<<<128, 128, LSTM_SMEM>>>(hxs, cxs, w_hh, out);
    loss_fin<<<1, 128>>>(out);
    head_kernel<<<M / 8, 256>>>(aw, ab, cw, cb, out);
}

// round 17
// speedup vs baseline: 1.2971x; 1.2971x over previous
#include <cuda_runtime.h>
#include <cuda_fp16.h>
#include <cstdint>
#include <cstddef>

// ---------------------------------------------------------------------------
// Problem dims
// ---------------------------------------------------------------------------
#define Bc 256
#define Tc 256
#define Dc 128
#define Ec 256
#define Hc 256
#define Ac 18

static constexpr size_t N_LOGITS = (size_t)Bc * Tc * Ac;
static constexpr size_t NGATE    = (size_t)Bc * Tc * Hc;
static constexpr size_t OFF_LOGITS = 0;
static constexpr size_t OFF_VALUES = OFF_LOGITS + N_LOGITS;
static constexpr size_t OFF_HT     = OFF_VALUES + (size_t)Bc * Tc;
static constexpr size_t OFF_CT     = OFF_HT + (size_t)Bc * Hc;
static constexpr size_t OFF_AR     = OFF_CT + (size_t)Bc * Hc;
static constexpr size_t OFF_TAR    = OFF_AR + 1;
static constexpr size_t OFF_I      = OFF_TAR + 1;
static constexpr size_t OFF_Fg     = OFF_I + NGATE;
static constexpr size_t OFF_Gg     = OFF_Fg + NGATE;
static constexpr size_t OFF_Og     = OFF_Gg + NGATE;
static constexpr size_t OFF_CS     = OFF_Og + NGATE;
static constexpr size_t OFF_HS     = OFF_CS + NGATE;

// ---------------------------------------------------------------------------
// Device scratch
// ---------------------------------------------------------------------------
__device__ float  g_pre [(size_t)Bc * Tc * 4 * Hc];
__device__ float  g_bias[4 * Hc];
__device__ float  g_part[256];
__device__ __half g_obs_h[(size_t)Bc * Tc * Dc];
__device__ __half g_obs_l[(size_t)Bc * Tc * Dc];
__device__ __half g_e1h[(size_t)Bc * Tc * Ec];
__device__ __half g_e1l[(size_t)Bc * Tc * Ec];
__device__ __half g_e2h[(size_t)Bc * Tc * Ec];
__device__ __half g_e2l[(size_t)Bc * Tc * Ec];
__device__ __half g_w1h[Ec * Dc];
__device__ __half g_w2h[Ec * Ec];
__device__ __half g_wih_h[4 * Hc * Ec];

extern __shared__ __align__(1024) char dynsmem[];

// ---------------------------------------------------------------------------
// Math helpers
// ---------------------------------------------------------------------------
__device__ __forceinline__ float sigm(float x) {
    return __fdividef(1.0f, 1.0f + __expf(-x));
}
__device__ __forceinline__ float tanh_f(float x) {
    return 1.0f - __fdividef(2.0f, __expf(2.0f * x) + 1.0f);
}
__device__ __forceinline__ float silu(float x) { return x * sigm(x); }

__device__ __forceinline__ uint32_t smem_u32(const void* p) {
    uint32_t a;
    asm("{ .reg .u64 t; cvta.to.shared.u64 t, %1; cvt.u32.u64 %0, t; }" : "=r"(a) : "l"(p));
    return a;
}

// ---------------------------------------------------------------------------
// warp-MMA + cp.async primitives (baseline PTX, valid at target sm_100)
// ---------------------------------------------------------------------------
__device__ __forceinline__ void ldsm4(uint32_t* r, uint32_t addr) {
    asm volatile("ldmatrix.sync.aligned.m8n8.x4.shared.b16 {%0,%1,%2,%3}, [%4];"
                 : "=r"(r[0]), "=r"(r[1]), "=r"(r[2]), "=r"(r[3]) : "r"(addr));
}
__device__ __forceinline__ void ldsm2(uint32_t* r, uint32_t addr) {
    asm volatile("ldmatrix.sync.aligned.m8n8.x2.shared.b16 {%0,%1}, [%2];"
                 : "=r"(r[0]), "=r"(r[1]) : "r"(addr));
}
__device__ __forceinline__ void mma16816h(float* d, const uint32_t* a, const uint32_t* b) {
    asm volatile("mma.sync.aligned.m16n8k16.row.col.f32.f16.f16.f32 "
                 "{%0,%1,%2,%3}, {%4,%5,%6,%7}, {%8,%9}, {%0,%1,%2,%3};"
                 : "+f"(d[0]), "+f"(d[1]), "+f"(d[2]), "+f"(d[3])
                 : "r"(a[0]), "r"(a[1]), "r"(a[2]), "r"(a[3]), "r"(b[0]), "r"(b[1]));
}
__device__ __forceinline__ void cp16(uint32_t dst, const void* src) {
    asm volatile("cp.async.cg.shared.global [%0], [%1], 16;" :: "r"(dst), "l"(src));
}
#define CP_COMMIT() asm volatile("cp.async.commit_group;" ::: "memory")

// ---------------------------------------------------------------------------
// fp32 -> fp16 conversions
// ---------------------------------------------------------------------------
__global__ void conv_split_h(const float* __restrict__ in, __half* __restrict__ h,
                             __half* __restrict__ l, int n)
{
    int i = blockIdx.x * blockDim.x + threadIdx.x;
    if (i >= n) return;
    float x = in[i];
    __half hb = __float2half_rn(x);
    h[i] = hb;
    l[i] = __float2half_rn(x - __half2float(hb));
}
__global__ void conv_h(const float* __restrict__ in, __half* __restrict__ h, int n)
{
    int i = blockIdx.x * blockDim.x + threadIdx.x;
    if (i >= n) return;
    h[i] = __float2half_rn(in[i]);
}

// ---------------------------------------------------------------------------
// split-fp16 tensor-core GEMM (unchanged from R8/R10/R14 passing kernel)
// ---------------------------------------------------------------------------
#define PA_H 0
#define PA_L 10240
#define PB_H 20480
#define GSTAGE 30720
#define GDATA_OFF 512
#define GEMM_SMEM_TOT (GDATA_OFF + 2 * GSTAGE)

__device__ __forceinline__ void gemm_load_stage(
    uint32_t sbase,
    const __half* __restrict__ Ah, const __half* __restrict__ Al,
    const __half* __restrict__ Wh,
    int m0, int n0, int K, int k0, int tid)
{
    #pragma unroll
    for (int i = 0; i < 2; ++i) {
        int idx = tid + (i << 8);
        int row = idx >> 2, c = idx & 3;
        uint32_t d = (uint32_t)(row * 80 + c * 16);
        size_t ga = (size_t)(m0 + row) * K + k0 + c * 8;
        size_t gb = (size_t)(n0 + row) * K + k0 + c * 8;
        cp16(sbase + PA_H + d, Ah + ga);
        cp16(sbase + PA_L + d, Al + ga);
        cp16(sbase + PB_H + d, Wh + gb);
    }
}

__global__ __launch_bounds__(256)
void gemm_mma(const __half* __restrict__ Ah, const __half* __restrict__ Al,
              const __half* __restrict__ Wh,
              const float* __restrict__ bias, float* __restrict__ outF,
              __half* __restrict__ outH, __half* __restrict__ outL,
              int K, int N, int mode)
{
    const uint32_t sb = smem_u32(dynsmem);
    float* sbias = (float*)dynsmem;

    const int tid  = threadIdx.x;
    const int lane = tid & 31;
    const int w    = tid >> 5;
    const int wm   = w >> 2;
    const int wn   = w & 3;
    const int m0   = blockIdx.x * 128;
    const int n0   = blockIdx.y * 128;

    if (tid < 128) sbias[tid] = bias[n0 + tid];

    const int aro  = (lane & 7) + ((lane >> 3) & 1) * 8;
    const int ac16 = (lane >> 4) & 1;
    const int bl8  = lane & 15;
    const int bro  = bl8 & 7;
    const int bc16 = (bl8 >> 3) & 1;

    const uint32_t aBase = (uint32_t)aro * 80 + ac16 * 16;
    const uint32_t bBase = (uint32_t)bro * 80 + bc16 * 16;

    float acc[4][4][4];
    #pragma unroll
    for (int mt = 0; mt < 4; ++mt)
        #pragma unroll
        for (int nt = 0; nt < 4; ++nt)
            #pragma unroll
            for (int r = 0; r < 4; ++r) acc[mt][nt][r] = 0.0f;

    const int NCH = K >> 5;
    gemm_load_stage(sb + GDATA_OFF, Ah, Al, Wh, m0, n0, K, 0, tid);
    CP_COMMIT();

    for (int ch = 0; ch < NCH; ++ch) {
        if (ch + 1 < NCH) {
            gemm_load_stage(sb + GDATA_OFF + ((ch + 1) & 1) * GSTAGE,
                            Ah, Al, Wh, m0, n0, K, (ch + 1) << 5, tid);
            CP_COMMIT();
            asm volatile("cp.async.wait_group 1;" ::: "memory");
        } else {
            asm volatile("cp.async.wait_group 0;" ::: "memory");
        }
        __syncthreads();

        const uint32_t st = sb + GDATA_OFF + (ch & 1) * GSTAGE;
        #pragma unroll
        for (int ks = 0; ks < 2; ++ks) {
            uint32_t bh[4][2];
            #pragma unroll
            for (int nt = 0; nt < 4; ++nt) {
                uint32_t o = bBase + (uint32_t)(wn * 32 + nt * 8) * 80 + ks * 32;
                ldsm2(bh[nt], st + PB_H + o);
            }
            #pragma unroll
            for (int mt = 0; mt < 4; ++mt) {
                uint32_t ah[4], al[4];
                uint32_t o = aBase + (uint32_t)(wm * 64 + mt * 16) * 80 + ks * 32;
                ldsm4(ah, st + PA_H + o);
                ldsm4(al, st + PA_L + o);
                #pragma unroll
                for (int nt = 0; nt < 4; ++nt) {
                    mma16816h(acc[mt][nt], ah, bh[nt]);
                    mma16816h(acc[mt][nt], al, bh[nt]);
                }
            }
        }
        __syncthreads();
    }

    #pragma unroll
    for (int mt = 0; mt < 4; ++mt) {
        const int r0 = m0 + wm * 64 + mt * 16 + (lane >> 2);
        #pragma unroll
        for (int nt = 0; nt < 4; ++nt) {
            const int cl = wn * 32 + nt * 8 + (lane & 3) * 2;
            const int c  = n0 + cl;
            float v0 = acc[mt][nt][0] + sbias[cl];
            float v1 = acc[mt][nt][1] + sbias[cl + 1];
            float v2 = acc[mt][nt][2] + sbias[cl];
            float v3 = acc[mt][nt][3] + sbias[cl + 1];
            if (mode == 0) {
                *(float2*)&outF[(size_t)r0 * N + c]       = make_float2(v0, v1);
                *(float2*)&outF[(size_t)(r0 + 8) * N + c] = make_float2(v2, v3);
            } else {
                v0 = silu(v0); v1 = silu(v1); v2 = silu(v2); v3 = silu(v3);
                __half h0 = __float2half_rn(v0), h1 = __float2half_rn(v1);
                __half h2 = __float2half_rn(v2), h3 = __float2half_rn(v3);
                __half l0 = __float2half_rn(v0 - __half2float(h0));
                __half l1 = __float2half_rn(v1 - __half2float(h1));
                __half l2 = __float2half_rn(v2 - __half2float(h2));
                __half l3 = __float2half_rn(v3 - __half2float(h3));
                size_t o0 = (size_t)r0 * N + c, o1 = (size_t)(r0 + 8) * N + c;
                *(__half2*)&outH[o0] = __halves2half2(h0, h1);
                *(__half2*)&outL[o0] = __halves2half2(l0, l1);
                *(__half2*)&outH[o1] = __halves2half2(h2, h3);
                *(__half2*)&outL[o1] = __halves2half2(l2, l3);
            }
        }
    }
}

// ---------------------------------------------------------------------------
// bias prep
// ---------------------------------------------------------------------------
__global__ void prep_bias(const float* __restrict__ bih, const float* __restrict__ bhh)
{
    int i = threadIdx.x;
    g_bias[i] = bih[i] + bhh[i];
}

// ---------------------------------------------------------------------------
// Tensor-core persistent cluster LSTM (R14 structure) with single-plane
// fp16 h recurrence: h-lo plane dropped -> 64 MMAs/step (was 128 in 2-pass
// hi/lo form... now 4 MMAs per kc), DSMEM exchange halved to 8 KB/step,
// LDSM count reduced. Gate stores remain R14 scalar __stcs in the
// arrive->wait window (R15/16 staging regressed and is reverted).
// ---------------------------------------------------------------------------
#define HSTR  264
#define SM_BH 0                            // Whh hi [128][HSTR]       (67584 B)
#define SM_A0 (128 * HSTR * 2)             // h buf0: hi[16][HSTR]     (67584)
#define ABUF  (16 * HSTR * 2)              // 8448 per buffer (hi only)
#define SM_A1 (SM_A0 + ABUF)               // 76032
#define SM_STG (SM_A1 + ABUF)              // 84480: stage_h [16][32] halves
#define LSTM_SMEM (SM_STG + 16 * 32 * 2)   // 85504

__global__ void __cluster_dims__(8, 1, 1) __launch_bounds__(128, 1)
lstm_kernel(const float* __restrict__ hxs, const float* __restrict__ cxs,
            const float* __restrict__ w_hh, float* __restrict__ out)
{
    char* smc = dynsmem;
    const uint32_t sb = smem_u32(dynsmem);
    const int tid  = threadIdx.x;
    const int lane = tid & 31;
    const int w    = tid >> 5;
    const int grp  = blockIdx.x >> 3;
    const int rank = blockIdx.x & 7;
    const int b0   = grp * 16;
    const int u0   = rank * 32;

    // Whh hi plane: row n = lu*4 + q  <-  w_hh[q*256 + u0 + lu][:]
    {
        int lu = tid >> 2, q = tid & 3;
        const float* src = &w_hh[(size_t)((q << 8) + u0 + lu) * Hc];
        __half* bh = (__half*)(smc + SM_BH) + tid * HSTR;
        for (int k = 0; k < Hc; k += 4) {
            float4 v = *(const float4*)&src[k];
            bh[k + 0] = __float2half_rn(v.x);
            bh[k + 1] = __float2half_rn(v.y);
            bh[k + 2] = __float2half_rn(v.z);
            bh[k + 3] = __float2half_rn(v.w);
        }
    }
    // init h buffer 0 from hxs (hi plane only)
    for (int idx = tid; idx < 16 * 64; idx += 128) {
        int row = idx >> 6, k4 = (idx & 63) << 2;
        float4 v = *(const float4*)&hxs[(size_t)(b0 + row) * Hc + k4];
        __half* ah = (__half*)(smc + SM_A0) + row * HSTR + k4;
        ah[0] = __float2half_rn(v.x);
        ah[1] = __float2half_rn(v.y);
        ah[2] = __float2half_rn(v.z);
        ah[3] = __float2half_rn(v.w);
    }

    unsigned ra0[8], ra1[8];
    {
        unsigned a0 = sb + SM_A0, a1 = sb + SM_A1;
        #pragma unroll
        for (int rk = 0; rk < 8; ++rk) {
            asm volatile("mapa.shared::cluster.u32 %0, %1, %2;" : "=r"(ra0[rk]) : "r"(a0), "r"(rk));
            asm volatile("mapa.shared::cluster.u32 %0, %1, %2;" : "=r"(ra1[rk]) : "r"(a1), "r"(rk));
        }
    }

    // thread/cell geometry (R9/R10-proven)
    const int d_    = (lane & 3) >> 1;
    const bool isT0 = ((lane & 1) == 0);
    const int r1    = lane >> 2;
    const int myrow = r1 + ((lane & 1) << 3);
    const int q0    = (lane & 1) ? 2 : 0;

    float c[4], hp[4];
    int lcs[4];
    #pragma unroll
    for (int s = 0; s < 4; ++s) {
        lcs[s] = 8 * w + 2 * s + d_;
        c[s]  = cxs[(size_t)(b0 + myrow) * Hc + u0 + lcs[s]];
        hp[s] = 0.0f;
    }
    float ar = 0.0f, tar = 0.0f;

    const uint32_t aoff = (uint32_t)((lane & 7) + ((lane >> 3) & 1) * 8) * 528
                        + (uint32_t)((lane >> 4) & 1) * 16;
    const uint32_t bofs0 = (uint32_t)(32 * w) * 528 + aoff;
    const uint32_t bofs1 = (uint32_t)(32 * w + 16) * 528 + aoff;

    __half* stage_h = (__half*)(smc + SM_STG);

    __syncthreads();

    // prefetch g_pre for t=0
    float pre[4][4];
    {
        size_t p1 = ((size_t)((b0 + r1) * Tc)) * 1024;
        size_t p2 = ((size_t)((b0 + r1 + 8) * Tc)) * 1024;
        #pragma unroll
        for (int s = 0; s < 4; ++s) {
            int col = q0 * 256 + u0 + lcs[s];
            pre[s][0] = g_pre[p1 + col]; pre[s][1] = g_pre[p1 + col + 256];
            pre[s][2] = g_pre[p2 + col]; pre[s][3] = g_pre[p2 + col + 256];
        }
    }

    int cur = 0;
    for (int t = 0; t < Tc; ++t) {
        float acc[4][4], acc2[4][4];
        #pragma unroll
        for (int s = 0; s < 4; ++s) {
            acc[s][0] = pre[s][0]; acc[s][1] = pre[s][1];
            acc[s][2] = pre[s][2]; acc[s][3] = pre[s][3];
            acc2[s][0] = 0.0f; acc2[s][1] = 0.0f;
            acc2[s][2] = 0.0f; acc2[s][3] = 0.0f;
        }

        const uint32_t abh = sb + (cur ? SM_A1 : SM_A0);

        // software-pipelined mainloop: frags for kc+1 load before MMAs of kc
        uint32_t fah[2][4], f0[2][4], f1[2][4];
        ldsm4(fah[0], abh + aoff);
        ldsm4(f0[0],  sb + SM_BH + bofs0);
        ldsm4(f1[0],  sb + SM_BH + bofs1);

        #pragma unroll
        for (int kc = 0; kc < 16; ++kc) {
            const int cb = kc & 1, nb = cb ^ 1;
            if (kc < 15) {
                const uint32_t ko = (uint32_t)(kc + 1) * 32;
                ldsm4(fah[nb], abh + aoff + ko);
                ldsm4(f0[nb],  sb + SM_BH + bofs0 + ko);
                ldsm4(f1[nb],  sb + SM_BH + bofs1 + ko);
            }
            uint32_t bh[4][2] = {{f0[cb][0], f0[cb][2]}, {f0[cb][1], f0[cb][3]},
                                 {f1[cb][0], f1[cb][2]}, {f1[cb][1], f1[cb][3]}};
            float (*A)[4] = cb ? acc2 : acc;
            #pragma unroll
            for (int s = 0; s < 4; ++s)
                mma16816h(A[s], fah[cb], bh[s]);
        }
        #pragma unroll
        for (int s = 0; s < 4; ++s) {
            acc[s][0] += acc2[s][0]; acc[s][1] += acc2[s][1];
            acc[s][2] += acc2[s][2]; acc[s][3] += acc2[s][3];
        }

        // pointwise cell (values kept in registers; stores deferred)
        float iv[4], fv[4], gv[4], ov[4], c2a[4], h2a[4];
        #pragma unroll
        for (int s = 0; s < 4; ++s) {
            float sh1 = __shfl_xor_sync(0xffffffffu, isT0 ? acc[s][2] : acc[s][0], 1);
            float sh2 = __shfl_xor_sync(0xffffffffu, isT0 ? acc[s][3] : acc[s][1], 1);
            float i_, f_, g_, o_;
            if (isT0) { i_ = acc[s][0]; f_ = acc[s][1]; g_ = sh1; o_ = sh2; }
            else      { g_ = acc[s][2]; o_ = acc[s][3]; i_ = sh1; f_ = sh2; }

            iv[s] = sigm(i_); fv[s] = sigm(f_); gv[s] = tanh_f(g_); ov[s] = sigm(o_);
            float c2 = fmaf(fv[s], c[s], iv[s] * gv[s]);
            float h2 = ov[s] * tanh_f(c2);
            c2a[s] = c2; h2a[s] = h2;
            c[s] = c2;
            ar = fmaf(h2, h2, ar);
            float dd = h2 - hp[s];
            if (t > 0) tar = fmaf(dd, dd, tar);
            hp[s] = h2;

            stage_h[myrow * 32 + lcs[s]] = __float2half_rn(h2);
        }

        __syncthreads();

        // push own 32-unit h chunk (hi plane, 1 KB) to all 8 ranks: 8B/thread
        {
            const int row = tid >> 3;           // 0..15
            const int ch  = tid & 7;            // 4-unit chunk
            uint2 v = *(const uint2*)(smc + SM_STG + (row * 32 + ch * 4) * 2);
            const uint32_t dsto = (uint32_t)row * 528 + (uint32_t)(u0 + ch * 4) * 2;
            const unsigned* rbuf = cur ? ra0 : ra1;
            #pragma unroll
            for (int rk = 0; rk < 8; ++rk) {
                asm volatile("st.shared::cluster.v2.b32 [%0], {%1,%2};"
                             :: "r"(rbuf[rk] + dsto), "r"(v.x), "r"(v.y)
                             : "memory");
            }
        }

        asm volatile("barrier.cluster.arrive.aligned;" ::: "memory");

        // hidden inside arrive->wait: gate stores + next-step pre prefetch
        #pragma unroll
        for (int s = 0; s < 4; ++s) {
            const int grow = b0 + myrow;
            const int unit = u0 + lcs[s];
            const size_t base = ((size_t)(grow * Tc + t)) * Hc + unit;
            __stcs(&out[OFF_I  + base], iv[s]);
            __stcs(&out[OFF_Fg + base], fv[s]);
            __stcs(&out[OFF_Gg + base], gv[s]);
            __stcs(&out[OFF_Og + base], ov[s]);
            __stcs(&out[OFF_CS + base], c2a[s]);
            __stcs(&out[OFF_HS + base], h2a[s]);
            if (t == Tc - 1) {
                out[OFF_HT + (size_t)grow * Hc + unit] = h2a[s];
                out[OFF_CT + (size_t)grow * Hc + unit] = c2a[s];
            }
        }
        if (t + 1 < Tc) {
            size_t p1 = ((size_t)((b0 + r1) * Tc + t + 1)) * 1024;
            size_t p2 = ((size_t)((b0 + r1 + 8) * Tc + t + 1)) * 1024;
            #pragma unroll
            for (int s = 0; s < 4; ++s) {
                int col = q0 * 256 + u0 + lcs[s];
                pre[s][0] = g_pre[p1 + col]; pre[s][1] = g_pre[p1 + col + 256];
                pre[s][2] = g_pre[p2 + col]; pre[s][3] = g_pre[p2 + col + 256];
            }
        }

        asm volatile("barrier.cluster.wait.aligned;" ::: "memory");
        cur ^= 1;
    }

    __shared__ float red[128];
    red[tid] = ar; __syncthreads();
    for (int o = 64; o > 0; o >>= 1) { if (tid < o) red[tid] += red[tid + o]; __syncthreads(); }
    if (tid == 0) g_part[blockIdx.x] = red[0];
    __syncthreads();
    red[tid] = tar; __syncthreads();
    for (int o = 64; o > 0; o >>= 1) { if (tid < o) red[tid] += red[tid + o]; __syncthreads(); }
    if (tid == 0) g_part[128 + blockIdx.x] = red[0];
}

// ---------------------------------------------------------------------------
// loss finalize
// ---------------------------------------------------------------------------
__global__ void loss_fin(float* __restrict__ out)
{
    __shared__ float r[128];
    int tid = threadIdx.x;
    r[tid] = g_part[tid]; __syncthreads();
    for (int o = 64; o > 0; o >>= 1) { if (tid < o) r[tid] += r[tid + o]; __syncthreads(); }
    float sar = r[0]; __syncthreads();
    r[tid] = g_part[128 + tid]; __syncthreads();
    for (int o = 64; o > 0; o >>= 1) { if (tid < o) r[tid] += r[tid + o]; __syncthreads(); }
    if (tid == 0) {
        out[OFF_AR]  = sar * (0.01f / 16777216.0f);
        out[OFF_TAR] = r[0] * (0.01f / 16711680.0f);
    }
}

// ---------------------------------------------------------------------------
// actor/critic heads
// ---------------------------------------------------------------------------
__global__ __launch_bounds__(256)
void head_kernel(const float* __restrict__ aw, const float* __restrict__ ab,
                 const float* __restrict__ cw, const float* __restrict__ cb,
                 float* __restrict__ out)
{
    __shared__ float ws[19 * 256];
    const int tid = threadIdx.x;
    for (int i = tid; i < Ac * Hc; i += 256) ws[i] = aw[i];
    for (int i = tid; i < Hc; i += 256) ws[Ac * Hc + i] = cw[i];
    __syncthreads();

    const int warp = tid >> 5, lane = tid & 31;
    const size_t m = (size_t)blockIdx.x * 8 + warp;
    const float* h = &out[OFF_HS + m * Hc];

    float p[19];
    #pragma unroll
    for (int o = 0; o < 19; ++o) p[o] = 0.0f;
    #pragma unroll
    for (int kk = 0; kk < 8; ++kk) {
        int k = lane + kk * 32;
        float hv = h[k];
        #pragma unroll
        for (int o = 0; o < 19; ++o) p[o] = fmaf(hv, ws[o * 256 + k], p[o]);
    }
    #pragma unroll
    for (int o = 0; o < 19; ++o)
        #pragma unroll
        for (int off = 16; off > 0; off >>= 1)
            p[o] += __shfl_down_sync(0xffffffffu, p[o], off);

    if (lane == 0) {
        #pragma unroll
        for (int o = 0; o < Ac; ++o)
            out[OFF_LOGITS + m * Ac + o] = p[o] + ab[o];
        out[OFF_VALUES + m] = p[18] + cb[0];
    }
}

// ---------------------------------------------------------------------------
// launcher
// ---------------------------------------------------------------------------
extern "C" void kernel_launch(void* const* d_in, const int* in_sizes, int n_in,
                              void* d_out, int out_size)
{
    const float* obs    = (const float*)d_in[0];
    const float* hxs    = (const float*)d_in[1];
    const float* cxs    = (const float*)d_in[2];
    const float* enc_w1 = (const float*)d_in[3];
    const float* enc_b1 = (const float*)d_in[4];
    const float* enc_w2 = (const float*)d_in[5];
    const float* enc_b2 = (const float*)d_in[6];
    const float* w_ih   = (const float*)d_in[7];
    const float* w_hh   = (const float*)d_in[8];
    const float* b_ih   = (const float*)d_in[9];
    const float* b_hh   = (const float*)d_in[10];
    const float* aw     = (const float*)d_in[11];
    const float* ab     = (const float*)d_in[12];
    const float* cw     = (const float*)d_in[13];
    const float* cb     = (const float*)d_in[14];
    float* out = (float*)d_out;

    void *p_pre, *p_bias;
    void *p_oh, *p_ol, *p_e1h, *p_e1l, *p_e2h, *p_e2l;
    void *p_w1h, *p_w2h, *p_wihh;
    cudaGetSymbolAddress(&p_pre,  g_pre);
    cudaGetSymbolAddress(&p_bias, g_bias);
    cudaGetSymbolAddress(&p_oh,   g_obs_h);  cudaGetSymbolAddress(&p_ol,   g_obs_l);
    cudaGetSymbolAddress(&p_e1h,  g_e1h);    cudaGetSymbolAddress(&p_e1l,  g_e1l);
    cudaGetSymbolAddress(&p_e2h,  g_e2h);    cudaGetSymbolAddress(&p_e2l,  g_e2l);
    cudaGetSymbolAddress(&p_w1h,  g_w1h);
    cudaGetSymbolAddress(&p_w2h,  g_w2h);
    cudaGetSymbolAddress(&p_wihh, g_wih_h);

    cudaFuncSetAttribute(lstm_kernel,
                         cudaFuncAttributeMaxDynamicSharedMemorySize, LSTM_SMEM);
    cudaFuncSetAttribute(gemm_mma,
                         cudaFuncAttributeMaxDynamicSharedMemorySize, GEMM_SMEM_TOT);

    const int M = Bc * Tc;  // 65536

    {
        int n;
        n = M * Dc;      conv_split_h<<<(n + 255) / 256, 256>>>(obs, (__half*)p_oh, (__half*)p_ol, n);
        n = Ec * Dc;     conv_h<<<(n + 255) / 256, 256>>>(enc_w1, (__half*)p_w1h, n);
        n = Ec * Ec;     conv_h<<<(n + 255) / 256, 256>>>(enc_w2, (__half*)p_w2h, n);
        n = 4 * Hc * Ec; conv_h<<<(n + 255) / 256, 256>>>(w_ih,   (__half*)p_wihh, n);
    }
    prep_bias<<<1, 1024>>>(b_ih, b_hh);

    gemm_mma<<<dim3(M / 128, Ec / 128), 256, GEMM_SMEM_TOT>>>(
        (const __half*)p_oh, (const __half*)p_ol, (const __half*)p_w1h,
        enc_b1, nullptr, (__half*)p_e1h, (__half*)p_e1l, Dc, Ec, 1);
    gemm_mma<<<dim3(M / 128, Ec / 128), 256, GEMM_SMEM_TOT>>>(
        (const __half*)p_e1h, (const __half*)p_e1l, (const __half*)p_w2h,
        enc_b2, nullptr, (__half*)p_e2h, (__half*)p_e2l, Ec, Ec, 1);
    gemm_mma<<<dim3(M / 128, (4 * Hc) / 128), 256, GEMM_SMEM_TOT>>>(
        (const __half*)p_e2h, (const __half*)p_e2l, (const __half*)p_wihh,
        (const float*)p_bias, (float*)p_pre, nullptr, nullptr, Ec, 4 * Hc, 0);

    lstm_kernel<<<128, 128, LSTM_SMEM>>>(hxs, cxs, w_hh, out);
    loss_fin<<<1, 128>>>(out);
    head_kernel<<<M / 8, 256>>>(aw, ab, cw, cb, out);
}